// round 4
// baseline (speedup 1.0000x reference)
#include <cuda_runtime.h>
#include <cuda_bf16.h>
#include <math.h>
#include <stdint.h>

#define BATCH 2
#define SEQ   4096
#define DM    1024
#define NH    16
#define DH    64
#define L3    3072
#define ROWS  (BATCH*SEQ)

// ---------------- device scratch (allocation-free) ----------------
__device__ float g_qkv[(size_t)ROWS * L3];                     // fp32 qkv gemm output
__device__ __nv_bfloat16 g_xh[(size_t)ROWS*DM],  g_xl[(size_t)ROWS*DM];
__device__ __nv_bfloat16 g_wqh[(size_t)DM*L3],   g_wql[(size_t)DM*L3];   // w_qkv^T [3072][1024]
__device__ __nv_bfloat16 g_woh[(size_t)DM*DM],   g_wol[(size_t)DM*DM];   // w_out^T [1024][1024]
__device__ __nv_bfloat16 g_Qh[(size_t)ROWS*DM],  g_Ql[(size_t)ROWS*DM];  // [b][h][l][64], pre-scaled
__device__ __nv_bfloat16 g_Kh[(size_t)ROWS*DM],  g_Kl[(size_t)ROWS*DM];  // [b][h][l][64]
__device__ __nv_bfloat16 g_Vh[(size_t)ROWS*DM],  g_Vl[(size_t)ROWS*DM];  // [b][h][d][SEQ]
__device__ __nv_bfloat16 g_ath[(size_t)ROWS*DM], g_atl[(size_t)ROWS*DM]; // attention out

// ---------------- helpers ----------------
__device__ __forceinline__ uint32_t pack2(__nv_bfloat16 a, __nv_bfloat16 b) {
    __nv_bfloat162 t; t.x = a; t.y = b;
    return *reinterpret_cast<uint32_t*>(&t);
}
__device__ __forceinline__ void split1(float f, __nv_bfloat16& h, __nv_bfloat16& l) {
    h = __float2bfloat16_rn(f);
    l = __float2bfloat16_rn(f - __bfloat162float(h));
}
__device__ __forceinline__ void split_pack2(float f0, float f1, uint32_t& h, uint32_t& l) {
    __nv_bfloat16 h0, l0, h1, l1;
    split1(f0, h0, l0); split1(f1, h1, l1);
    h = pack2(h0, h1); l = pack2(l0, l1);
}
__device__ __forceinline__ void mma_bf16(float c[4],
                                         uint32_t a0, uint32_t a1, uint32_t a2, uint32_t a3,
                                         uint32_t b0, uint32_t b1) {
    asm volatile(
        "mma.sync.aligned.m16n8k16.row.col.f32.bf16.bf16.f32 "
        "{%0,%1,%2,%3}, {%4,%5,%6,%7}, {%8,%9}, {%0,%1,%2,%3};\n"
        : "+f"(c[0]), "+f"(c[1]), "+f"(c[2]), "+f"(c[3])
        : "r"(a0), "r"(a1), "r"(a2), "r"(a3), "r"(b0), "r"(b1));
}
#define LDSM4(r0,r1,r2,r3,addr) \
    asm volatile("ldmatrix.sync.aligned.m8n8.x4.shared.b16 {%0,%1,%2,%3}, [%4];" \
                 : "=r"(r0),"=r"(r1),"=r"(r2),"=r"(r3) : "r"(addr))
#define CP16(s,g)  asm volatile("cp.async.cg.shared.global [%0], [%1], 16;" :: "r"(s), "l"(g))
#define CPCOMMIT() asm volatile("cp.async.commit_group;" ::: "memory")
#define CPWAIT1()  asm volatile("cp.async.wait_group 1;" ::: "memory")

// ---------------------------------------------------------------------------
// prep: transpose + split weights:  W[K][N] fp32  ->  WT_h/l[N][K] bf16
// ---------------------------------------------------------------------------
__global__ void prep_wT(const float* __restrict__ W,
                        __nv_bfloat16* __restrict__ WTh, __nv_bfloat16* __restrict__ WTl,
                        int K, int N)
{
    __shared__ float t[32][33];
    const int tid = threadIdx.x;
    const int n0 = blockIdx.x * 32, k0 = blockIdx.y * 32;
    #pragma unroll
    for (int i = 0; i < 4; i++) {
        int idx = i * 256 + tid;
        int r = idx >> 5, c = idx & 31;
        t[r][c] = W[(size_t)(k0 + r) * N + n0 + c];
    }
    __syncthreads();
    uint32_t* oh = (uint32_t*)WTh;
    uint32_t* ol = (uint32_t*)WTl;
    #pragma unroll
    for (int i = 0; i < 2; i++) {
        int idx = i * 256 + tid;
        int n = idx >> 4, kp = idx & 15;
        uint32_t h, l;
        split_pack2(t[2*kp][n], t[2*kp+1][n], h, l);
        size_t o = ((size_t)(n0 + n) * K + k0) / 2 + kp;
        oh[o] = h; ol[o] = l;
    }
}

// ---------------------------------------------------------------------------
// prep: split x (row-major, no transpose)
// ---------------------------------------------------------------------------
__global__ void prep_x(const float* __restrict__ x,
                       __nv_bfloat16* __restrict__ xh, __nv_bfloat16* __restrict__ xl)
{
    size_t i = (size_t)blockIdx.x * 256 + threadIdx.x;
    float2 v = ((const float2*)x)[i];
    uint32_t h, l;
    split_pack2(v.x, v.y, h, l);
    ((uint32_t*)xh)[i] = h;
    ((uint32_t*)xl)[i] = l;
}

// ---------------------------------------------------------------------------
// prep: RoPE + split qkv.  Q scaled by 1/8.  V transposed to [b][h][d][SEQ].
// grid (SEQ/64, NH, BATCH), 256 threads.
// ---------------------------------------------------------------------------
__global__ void prep_qkv(const float* __restrict__ qkv)
{
    __shared__ float vs[64][65];
    const int tid = threadIdx.x;
    const int lt = blockIdx.x, h = blockIdx.y, b = blockIdx.z;
    const size_t rowg = (size_t)b * SEQ + lt * 64;
    const size_t bh = (size_t)b * NH + h;

    uint32_t* Qh32 = (uint32_t*)g_Qh; uint32_t* Ql32 = (uint32_t*)g_Ql;
    uint32_t* Kh32 = (uint32_t*)g_Kh; uint32_t* Kl32 = (uint32_t*)g_Kl;
    uint32_t* Vh32 = (uint32_t*)g_Vh; uint32_t* Vl32 = (uint32_t*)g_Vl;

    #pragma unroll
    for (int i = 0; i < 4; i++) {
        int idx = i * 256 + tid;          // 0..1023
        int r = idx >> 4;                 // row in tile
        int j = idx & 15;                 // d-pair (d0 = 2j < 32)
        int l = lt * 64 + r;
        const float* row = qkv + (rowg + r) * L3;
        float f0 = powf(500.0f, -(float)(2*j)     * (1.0f/32.0f));
        float f1 = powf(500.0f, -(float)(2*j + 1) * (1.0f/32.0f));
        float s0, c0, s1, c1;
        sincosf((float)l * f0, &s0, &c0);
        sincosf((float)l * f1, &s1, &c1);
        size_t ob = (bh * SEQ + l) * 32;  // u32 row base (64 bf16 = 32 u32)
        // Q (scaled)
        {
            const float* q = row + h * 64;
            float t1a = q[2*j], t1b = q[2*j+1], t2a = q[2*j+32], t2b = q[2*j+33];
            uint32_t hh, ll;
            split_pack2((t1a*c0 - t2a*s0) * 0.125f, (t1b*c1 - t2b*s1) * 0.125f, hh, ll);
            Qh32[ob + j] = hh;      Ql32[ob + j] = ll;
            split_pack2((t1a*s0 + t2a*c0) * 0.125f, (t1b*s1 + t2b*c1) * 0.125f, hh, ll);
            Qh32[ob + 16 + j] = hh; Ql32[ob + 16 + j] = ll;
        }
        // K
        {
            const float* k = row + 1024 + h * 64;
            float t1a = k[2*j], t1b = k[2*j+1], t2a = k[2*j+32], t2b = k[2*j+33];
            uint32_t hh, ll;
            split_pack2(t1a*c0 - t2a*s0, t1b*c1 - t2b*s1, hh, ll);
            Kh32[ob + j] = hh;      Kl32[ob + j] = ll;
            split_pack2(t1a*s0 + t2a*c0, t1b*s1 + t2b*c1, hh, ll);
            Kh32[ob + 16 + j] = hh; Kl32[ob + 16 + j] = ll;
        }
    }
    // V transpose
    #pragma unroll
    for (int i = 0; i < 4; i++) {
        int idx = i * 256 + tid;
        int r = idx >> 4, c4 = (idx & 15) * 4;
        float4 v = *(const float4*)(qkv + (rowg + r) * L3 + 2048 + h * 64 + c4);
        vs[r][c4] = v.x; vs[r][c4+1] = v.y; vs[r][c4+2] = v.z; vs[r][c4+3] = v.w;
    }
    __syncthreads();
    #pragma unroll
    for (int i = 0; i < 8; i++) {
        int idx = i * 256 + tid;          // 0..2047
        int d = idx >> 5, lp = idx & 31;
        uint32_t hh, ll;
        split_pack2(vs[2*lp][d], vs[2*lp+1][d], hh, ll);
        size_t o = (bh * 64 + d) * (SEQ/2) + lt * 32 + lp;
        Vh32[o] = hh; Vl32[o] = ll;
    }
}

// ---------------------------------------------------------------------------
// Split-bf16 GEMM + bias.  A[M][K] h/l row-major, B[N][K] h/l row-major (=W^T).
// CTA 128x128, BK=32, cp.async double buffer, ldmatrix fragments.
// smem stage: Ah(10240) Al(10240) Bh(10240) Bl(10240) = 40960 B; rows padded to 80 B.
// ---------------------------------------------------------------------------
#define GS 40960
__global__ __launch_bounds__(256, 2)
void gemm_bf16(const __nv_bfloat16* __restrict__ Ah, const __nv_bfloat16* __restrict__ Al,
               const __nv_bfloat16* __restrict__ Bh, const __nv_bfloat16* __restrict__ Bl,
               const float* __restrict__ bias, float* __restrict__ C,
               int M, int N, int K)
{
    extern __shared__ char smc[];
    const uint32_t smb = (uint32_t)__cvta_generic_to_shared(smc);
    const int tid = threadIdx.x, lane = tid & 31;
    const int wm = (tid >> 5) & 1, wn = tid >> 6;
    const int m0 = blockIdx.y * 128, n0 = blockIdx.x * 128;

    // staging: thread -> (tile, 2 rows, 4 chunks each)
    const int tile = tid >> 6;
    const int r2 = (tid & 63) * 2;
    const __nv_bfloat16* gt = (tile == 0) ? Ah : (tile == 1) ? Al : (tile == 2) ? Bh : Bl;
    const int gr = ((tile < 2) ? m0 : n0) + r2;
    const char* g0 = (const char*)(gt + (size_t)gr * K);
    const char* g1 = g0 + (size_t)K * 2;
    const uint32_t s0 = smb + tile * 10240 + r2 * 80;

    float acc[4][4][4];
    #pragma unroll
    for (int i = 0; i < 4; i++)
        #pragma unroll
        for (int j = 0; j < 4; j++)
            #pragma unroll
            for (int k = 0; k < 4; k++) acc[i][j][k] = 0.0f;

    const int rowA = ((lane >> 3) & 1) * 8 + (lane & 7);
    const int colA = (lane >> 4) * 16;
    const int rowB = (lane >> 4) * 8 + (lane & 7);
    const int colB = ((lane >> 3) & 1) * 16;

    const int nk = K >> 5;
    #pragma unroll
    for (int c = 0; c < 4; c++) { CP16(s0 + c*16, g0 + c*16); CP16(s0 + 80 + c*16, g1 + c*16); }
    CPCOMMIT();

    for (int kt = 0; kt < nk; kt++) {
        if (kt + 1 < nk) {
            const char* ga = g0 + (size_t)(kt + 1) * 64;
            const char* gb = g1 + (size_t)(kt + 1) * 64;
            uint32_t sa = s0 + ((kt + 1) & 1) * GS;
            #pragma unroll
            for (int c = 0; c < 4; c++) { CP16(sa + c*16, ga + c*16); CP16(sa + 80 + c*16, gb + c*16); }
        }
        CPCOMMIT();
        CPWAIT1();
        __syncthreads();
        const uint32_t st = smb + (kt & 1) * GS;

        #pragma unroll
        for (int ks = 0; ks < 2; ks++) {
            uint32_t ah[4][4], al_[4][4];
            #pragma unroll
            for (int mt = 0; mt < 4; mt++) {
                uint32_t aa = st + (uint32_t)(wm * 64 + mt * 16 + rowA) * 80 + ks * 32 + colA;
                LDSM4(ah[mt][0], ah[mt][1], ah[mt][2], ah[mt][3], aa);
                LDSM4(al_[mt][0], al_[mt][1], al_[mt][2], al_[mt][3], aa + 10240);
            }
            #pragma unroll
            for (int ntp = 0; ntp < 2; ntp++) {
                uint32_t ba = st + 20480 + (uint32_t)(wn * 32 + ntp * 16 + rowB) * 80 + ks * 32 + colB;
                uint32_t bh0, bh1, bh2, bh3, bl0, bl1, bl2, bl3;
                LDSM4(bh0, bh1, bh2, bh3, ba);
                LDSM4(bl0, bl1, bl2, bl3, ba + 10240);
                #pragma unroll
                for (int mt = 0; mt < 4; mt++) {
                    mma_bf16(acc[mt][2*ntp],   ah[mt][0], ah[mt][1], ah[mt][2], ah[mt][3], bh0, bh1);
                    mma_bf16(acc[mt][2*ntp],   ah[mt][0], ah[mt][1], ah[mt][2], ah[mt][3], bl0, bl1);
                    mma_bf16(acc[mt][2*ntp],   al_[mt][0], al_[mt][1], al_[mt][2], al_[mt][3], bh0, bh1);
                    mma_bf16(acc[mt][2*ntp+1], ah[mt][0], ah[mt][1], ah[mt][2], ah[mt][3], bh2, bh3);
                    mma_bf16(acc[mt][2*ntp+1], ah[mt][0], ah[mt][1], ah[mt][2], ah[mt][3], bl2, bl3);
                    mma_bf16(acc[mt][2*ntp+1], al_[mt][0], al_[mt][1], al_[mt][2], al_[mt][3], bh2, bh3);
                }
            }
        }
        __syncthreads();
    }

    #pragma unroll
    for (int nt = 0; nt < 4; nt++) {
        int col = n0 + wn * 32 + nt * 8 + (lane & 3) * 2;
        float2 bs = *(const float2*)&bias[col];
        #pragma unroll
        for (int mt = 0; mt < 4; mt++) {
            int r = m0 + wm * 64 + mt * 16 + (lane >> 2);
            float2 v0 = { acc[mt][nt][0] + bs.x, acc[mt][nt][1] + bs.y };
            float2 v1 = { acc[mt][nt][2] + bs.x, acc[mt][nt][3] + bs.y };
            *(float2*)&C[(size_t)r * N + col]       = v0;
            *(float2*)&C[(size_t)(r + 8) * N + col] = v1;
        }
    }
}

// ---------------------------------------------------------------------------
// Flash attention, pure-bf16 inputs, cp.async double buffer, ldmatrix frags.
// smem: Qh(18432) Ql(18432) | 2 stages of { Kh Kl Vh Vl } (9216 each) = 110592 B
// rows padded to 144 B.
// ---------------------------------------------------------------------------
#define FQ     36864
#define FSTAGE 36864
#define FSM    (FQ + 2*FSTAGE)

__global__ __launch_bounds__(256, 2)
void flash_bf16(const __nv_bfloat16* __restrict__ Qh, const __nv_bfloat16* __restrict__ Ql,
                const __nv_bfloat16* __restrict__ Kh, const __nv_bfloat16* __restrict__ Kl,
                const __nv_bfloat16* __restrict__ Vh, const __nv_bfloat16* __restrict__ Vl)
{
    extern __shared__ char smc[];
    const uint32_t smb = (uint32_t)__cvta_generic_to_shared(smc);
    const int tid = threadIdx.x, lane = tid & 31, wid = tid >> 5;
    const int qt = blockIdx.x, h = blockIdx.y, b = blockIdx.z;
    const size_t bh = (size_t)b * NH + h;

    // Q staging: one row (128B) per thread, hi/lo by tid>>7
    {
        const int qtile = tid >> 7;
        const int qr = tid & 127;
        const __nv_bfloat16* qsrc = qtile ? Ql : Qh;
        const char* gq = (const char*)(qsrc + (bh * SEQ + (size_t)qt * 128 + qr) * 64);
        uint32_t sq = smb + qtile * 18432 + qr * 144;
        #pragma unroll
        for (int c = 0; c < 8; c++) CP16(sq + c*16, gq + c*16);
    }
    // K/V staging: one row per thread
    const int tile = tid >> 6;
    const int krow = tid & 63;
    const char* gkv;
    int gstride;
    if (tile == 0)      { gkv = (const char*)(Kh + (bh * SEQ + krow) * 64); gstride = 8192; }
    else if (tile == 1) { gkv = (const char*)(Kl + (bh * SEQ + krow) * 64); gstride = 8192; }
    else if (tile == 2) { gkv = (const char*)(Vh + (bh * 64 + krow) * SEQ); gstride = 128; }
    else                { gkv = (const char*)(Vl + (bh * 64 + krow) * SEQ); gstride = 128; }
    const uint32_t skv = smb + FQ + tile * 9216 + krow * 144;
    #pragma unroll
    for (int c = 0; c < 8; c++) CP16(skv + c*16, gkv + c*16);
    CPCOMMIT();

    float s[8][4], o[8][4];
    float m0r = -INFINITY, m1r = -INFINITY, l0r = 0.0f, l1r = 0.0f;
    #pragma unroll
    for (int i = 0; i < 8; i++)
        #pragma unroll
        for (int j = 0; j < 4; j++) o[i][j] = 0.0f;

    const int rowA = ((lane >> 3) & 1) * 8 + (lane & 7);
    const int colA = (lane >> 4) * 16;
    const int rowB = (lane >> 4) * 8 + (lane & 7);
    const int colB = ((lane >> 3) & 1) * 16;

    for (int t = 0; t < SEQ / 64; t++) {
        if (t < SEQ / 64 - 1) {
            const char* gp = gkv + (size_t)(t + 1) * gstride;
            uint32_t sp = skv + ((t + 1) & 1) * FSTAGE;
            #pragma unroll
            for (int c = 0; c < 8; c++) CP16(sp + c*16, gp + c*16);
        }
        CPCOMMIT();
        CPWAIT1();
        __syncthreads();
        const uint32_t kvb = smb + FQ + (t & 1) * FSTAGE;

        // ---- S = Q @ K^T (3-term split)
        #pragma unroll
        for (int i = 0; i < 8; i++)
            #pragma unroll
            for (int j = 0; j < 4; j++) s[i][j] = 0.0f;

        #pragma unroll
        for (int ks = 0; ks < 4; ks++) {
            uint32_t qa = smb + (uint32_t)(wid * 16 + rowA) * 144 + ks * 32 + colA;
            uint32_t qh0, qh1, qh2, qh3, ql0, ql1, ql2, ql3;
            LDSM4(qh0, qh1, qh2, qh3, qa);
            LDSM4(ql0, ql1, ql2, ql3, qa + 18432);
            #pragma unroll
            for (int ntp = 0; ntp < 4; ntp++) {
                uint32_t ka = kvb + (uint32_t)(ntp * 16 + rowB) * 144 + ks * 32 + colB;
                uint32_t kh0, kh1, kh2, kh3, kl0, kl1, kl2, kl3;
                LDSM4(kh0, kh1, kh2, kh3, ka);
                LDSM4(kl0, kl1, kl2, kl3, ka + 9216);
                mma_bf16(s[2*ntp],   qh0, qh1, qh2, qh3, kh0, kh1);
                mma_bf16(s[2*ntp],   qh0, qh1, qh2, qh3, kl0, kl1);
                mma_bf16(s[2*ntp],   ql0, ql1, ql2, ql3, kh0, kh1);
                mma_bf16(s[2*ntp+1], qh0, qh1, qh2, qh3, kh2, kh3);
                mma_bf16(s[2*ntp+1], qh0, qh1, qh2, qh3, kl2, kl3);
                mma_bf16(s[2*ntp+1], ql0, ql1, ql2, ql3, kh2, kh3);
            }
        }

        // ---- online softmax
        float mx0 = -INFINITY, mx1 = -INFINITY;
        #pragma unroll
        for (int nt = 0; nt < 8; nt++) {
            mx0 = fmaxf(mx0, fmaxf(s[nt][0], s[nt][1]));
            mx1 = fmaxf(mx1, fmaxf(s[nt][2], s[nt][3]));
        }
        mx0 = fmaxf(mx0, __shfl_xor_sync(0xffffffffu, mx0, 1));
        mx0 = fmaxf(mx0, __shfl_xor_sync(0xffffffffu, mx0, 2));
        mx1 = fmaxf(mx1, __shfl_xor_sync(0xffffffffu, mx1, 1));
        mx1 = fmaxf(mx1, __shfl_xor_sync(0xffffffffu, mx1, 2));
        float mn0 = fmaxf(m0r, mx0), mn1 = fmaxf(m1r, mx1);
        float a0 = __expf(m0r - mn0), a1 = __expf(m1r - mn1);
        float sum0 = 0.0f, sum1 = 0.0f;
        #pragma unroll
        for (int nt = 0; nt < 8; nt++) {
            s[nt][0] = __expf(s[nt][0] - mn0); sum0 += s[nt][0];
            s[nt][1] = __expf(s[nt][1] - mn0); sum0 += s[nt][1];
            s[nt][2] = __expf(s[nt][2] - mn1); sum1 += s[nt][2];
            s[nt][3] = __expf(s[nt][3] - mn1); sum1 += s[nt][3];
        }
        sum0 += __shfl_xor_sync(0xffffffffu, sum0, 1);
        sum0 += __shfl_xor_sync(0xffffffffu, sum0, 2);
        sum1 += __shfl_xor_sync(0xffffffffu, sum1, 1);
        sum1 += __shfl_xor_sync(0xffffffffu, sum1, 2);
        l0r = l0r * a0 + sum0;  l1r = l1r * a1 + sum1;
        m0r = mn0;              m1r = mn1;
        #pragma unroll
        for (int dt = 0; dt < 8; dt++) {
            o[dt][0] *= a0; o[dt][1] *= a0;
            o[dt][2] *= a1; o[dt][3] *= a1;
        }

        // ---- O += P @ V (register repack of P into A-frag layout, hi/lo)
        #pragma unroll
        for (int kt = 0; kt < 4; kt++) {
            uint32_t ah0, ah1, ah2, ah3, au0, au1, au2, au3;
            split_pack2(s[2*kt][0],   s[2*kt][1],   ah0, au0);
            split_pack2(s[2*kt][2],   s[2*kt][3],   ah1, au1);
            split_pack2(s[2*kt+1][0], s[2*kt+1][1], ah2, au2);
            split_pack2(s[2*kt+1][2], s[2*kt+1][3], ah3, au3);
            #pragma unroll
            for (int dtp = 0; dtp < 4; dtp++) {
                uint32_t va = kvb + 18432 + (uint32_t)(dtp * 16 + rowB) * 144 + kt * 32 + colB;
                uint32_t vh0, vh1, vh2, vh3, vl0, vl1, vl2, vl3;
                LDSM4(vh0, vh1, vh2, vh3, va);
                LDSM4(vl0, vl1, vl2, vl3, va + 9216);
                mma_bf16(o[2*dtp],   ah0, ah1, ah2, ah3, vh0, vh1);
                mma_bf16(o[2*dtp],   ah0, ah1, ah2, ah3, vl0, vl1);
                mma_bf16(o[2*dtp],   au0, au1, au2, au3, vh0, vh1);
                mma_bf16(o[2*dtp+1], ah0, ah1, ah2, ah3, vh2, vh3);
                mma_bf16(o[2*dtp+1], ah0, ah1, ah2, ah3, vl2, vl3);
                mma_bf16(o[2*dtp+1], au0, au1, au2, au3, vh2, vh3);
            }
        }
        __syncthreads();
    }

    // ---- epilogue: normalize, split, pair-packed bf16 h/l to g_ath/g_atl
    float inv0 = 1.0f / l0r, inv1 = 1.0f / l1r;
    const size_t row = (size_t)b * SEQ + (size_t)qt * 128 + wid * 16 + (lane >> 2);
    uint32_t* oh32 = (uint32_t*)g_ath;
    uint32_t* ol32 = (uint32_t*)g_atl;
    #pragma unroll
    for (int dt = 0; dt < 8; dt++) {
        int cp = h * 32 + dt * 4 + (lane & 3);
        uint32_t hh, ll;
        split_pack2(o[dt][0] * inv0, o[dt][1] * inv0, hh, ll);
        oh32[row * 512 + cp] = hh;       ol32[row * 512 + cp] = ll;
        split_pack2(o[dt][2] * inv1, o[dt][3] * inv1, hh, ll);
        oh32[(row + 8) * 512 + cp] = hh; ol32[(row + 8) * 512 + cp] = ll;
    }
}

// ---------------------------------------------------------------------------
// Launcher
// ---------------------------------------------------------------------------
extern "C" void kernel_launch(void* const* d_in, const int* in_sizes, int n_in,
                              void* d_out, int out_size)
{
    const float* x     = (const float*)d_in[0];
    const float* w_qkv = (const float*)d_in[1];
    const float* b_qkv = (const float*)d_in[2];
    const float* w_out = (const float*)d_in[3];
    const float* b_out = (const float*)d_in[4];
    float* out = (float*)d_out;

    float* qkvp;
    __nv_bfloat16 *xh, *xl, *wqh, *wql, *woh, *wol, *Qh, *Ql, *Kh, *Kl, *Vh, *Vl, *ath, *atl;
    cudaGetSymbolAddress((void**)&qkvp, g_qkv);
    cudaGetSymbolAddress((void**)&xh, g_xh);   cudaGetSymbolAddress((void**)&xl, g_xl);
    cudaGetSymbolAddress((void**)&wqh, g_wqh); cudaGetSymbolAddress((void**)&wql, g_wql);
    cudaGetSymbolAddress((void**)&woh, g_woh); cudaGetSymbolAddress((void**)&wol, g_wol);
    cudaGetSymbolAddress((void**)&Qh, g_Qh);   cudaGetSymbolAddress((void**)&Ql, g_Ql);
    cudaGetSymbolAddress((void**)&Kh, g_Kh);   cudaGetSymbolAddress((void**)&Kl, g_Kl);
    cudaGetSymbolAddress((void**)&Vh, g_Vh);   cudaGetSymbolAddress((void**)&Vl, g_Vl);
    cudaGetSymbolAddress((void**)&ath, g_ath); cudaGetSymbolAddress((void**)&atl, g_atl);

    cudaFuncSetAttribute(gemm_bf16,  cudaFuncAttributeMaxDynamicSharedMemorySize, 2 * GS);
    cudaFuncSetAttribute(flash_bf16, cudaFuncAttributeMaxDynamicSharedMemorySize, FSM);

    // prep: weights (transpose+split), x (split)
    prep_wT<<<dim3(L3 / 32, DM / 32), 256>>>(w_qkv, wqh, wql, DM, L3);
    prep_wT<<<dim3(DM / 32, DM / 32), 256>>>(w_out, woh, wol, DM, DM);
    prep_x<<<(int)(((size_t)ROWS * DM / 2) / 256), 256>>>(x, xh, xl);

    // QKV projection (fp32 out + bias)
    gemm_bf16<<<dim3(L3 / 128, ROWS / 128), 256, 2 * GS>>>(xh, xl, wqh, wql, b_qkv, qkvp,
                                                           ROWS, L3, DM);
    // RoPE + split + V transpose
    prep_qkv<<<dim3(SEQ / 64, NH, BATCH), 256>>>(qkvp);

    // flash attention -> g_ath/g_atl (bf16 h/l)
    flash_bf16<<<dim3(SEQ / 128, NH, BATCH), 256, FSM>>>(Qh, Ql, Kh, Kl, Vh, Vl);

    // output projection
    gemm_bf16<<<dim3(DM / 128, ROWS / 128), 256, 2 * GS>>>(ath, atl, woh, wol, b_out, out,
                                                           ROWS, DM, DM);
}

// round 8
// speedup vs baseline: 1.0358x; 1.0358x over previous
#include <cuda_runtime.h>
#include <cuda_bf16.h>
#include <math.h>
#include <stdint.h>

#define BATCH 2
#define SEQ   4096
#define DM    1024
#define NH    16
#define DH    64
#define L3    3072
#define ROWS  (BATCH*SEQ)

// ---------------- device scratch (allocation-free) ----------------
__device__ float g_qkv[(size_t)ROWS * L3];
__device__ __nv_bfloat16 g_xh[(size_t)ROWS*DM],  g_xl[(size_t)ROWS*DM];
__device__ __nv_bfloat16 g_wqh[(size_t)DM*L3],   g_wql[(size_t)DM*L3];
__device__ __nv_bfloat16 g_woh[(size_t)DM*DM],   g_wol[(size_t)DM*DM];
__device__ __nv_bfloat16 g_Qh[(size_t)ROWS*DM],  g_Ql[(size_t)ROWS*DM];
__device__ __nv_bfloat16 g_Kh[(size_t)ROWS*DM],  g_Kl[(size_t)ROWS*DM];
__device__ __nv_bfloat16 g_Vh[(size_t)ROWS*DM],  g_Vl[(size_t)ROWS*DM];
__device__ __nv_bfloat16 g_ath[(size_t)ROWS*DM], g_atl[(size_t)ROWS*DM];

// ---------------- helpers ----------------
__device__ __forceinline__ uint32_t pack2(__nv_bfloat16 a, __nv_bfloat16 b) {
    __nv_bfloat162 t; t.x = a; t.y = b;
    return *reinterpret_cast<uint32_t*>(&t);
}
__device__ __forceinline__ void split1(float f, __nv_bfloat16& h, __nv_bfloat16& l) {
    h = __float2bfloat16_rn(f);
    l = __float2bfloat16_rn(f - __bfloat162float(h));
}
__device__ __forceinline__ void split_pack2(float f0, float f1, uint32_t& h, uint32_t& l) {
    __nv_bfloat16 h0, l0, h1, l1;
    split1(f0, h0, l0); split1(f1, h1, l1);
    h = pack2(h0, h1); l = pack2(l0, l1);
}
__device__ __forceinline__ void mma_bf16(float c[4],
                                         uint32_t a0, uint32_t a1, uint32_t a2, uint32_t a3,
                                         uint32_t b0, uint32_t b1) {
    asm volatile(
        "mma.sync.aligned.m16n8k16.row.col.f32.bf16.bf16.f32 "
        "{%0,%1,%2,%3}, {%4,%5,%6,%7}, {%8,%9}, {%0,%1,%2,%3};\n"
        : "+f"(c[0]), "+f"(c[1]), "+f"(c[2]), "+f"(c[3])
        : "r"(a0), "r"(a1), "r"(a2), "r"(a3), "r"(b0), "r"(b1));
}
#define LDSM4(r0,r1,r2,r3,addr) \
    asm volatile("ldmatrix.sync.aligned.m8n8.x4.shared.b16 {%0,%1,%2,%3}, [%4];" \
                 : "=r"(r0),"=r"(r1),"=r"(r2),"=r"(r3) : "r"(addr))
#define CP16(s,g)  asm volatile("cp.async.cg.shared.global [%0], [%1], 16;" :: "r"(s), "l"(g))
#define CPCOMMIT() asm volatile("cp.async.commit_group;" ::: "memory")
#define CPWAIT1()  asm volatile("cp.async.wait_group 1;" ::: "memory")
#define CPWAIT0()  asm volatile("cp.async.wait_group 0;" ::: "memory")

// ---------------- prep kernels ----------------
__global__ void prep_wT(const float* __restrict__ W,
                        __nv_bfloat16* __restrict__ WTh, __nv_bfloat16* __restrict__ WTl,
                        int K, int N)
{
    __shared__ float t[32][33];
    const int tid = threadIdx.x;
    const int n0 = blockIdx.x * 32, k0 = blockIdx.y * 32;
    #pragma unroll
    for (int i = 0; i < 4; i++) {
        int idx = i * 256 + tid;
        t[idx >> 5][idx & 31] = W[(size_t)(k0 + (idx >> 5)) * N + n0 + (idx & 31)];
    }
    __syncthreads();
    uint32_t* oh = (uint32_t*)WTh;
    uint32_t* ol = (uint32_t*)WTl;
    #pragma unroll
    for (int i = 0; i < 2; i++) {
        int idx = i * 256 + tid;
        int n = idx >> 4, kp = idx & 15;
        uint32_t h, l;
        split_pack2(t[2*kp][n], t[2*kp+1][n], h, l);
        size_t o = ((size_t)(n0 + n) * K + k0) / 2 + kp;
        oh[o] = h; ol[o] = l;
    }
}

__global__ void prep_x(const float* __restrict__ x,
                       __nv_bfloat16* __restrict__ xh, __nv_bfloat16* __restrict__ xl)
{
    size_t i = (size_t)blockIdx.x * 256 + threadIdx.x;
    float2 v = ((const float2*)x)[i];
    uint32_t h, l;
    split_pack2(v.x, v.y, h, l);
    ((uint32_t*)xh)[i] = h;
    ((uint32_t*)xl)[i] = l;
}

__global__ void prep_qkv(const float* __restrict__ qkv)
{
    __shared__ float vs[64][65];
    const int tid = threadIdx.x;
    const int lt = blockIdx.x, h = blockIdx.y, b = blockIdx.z;
    const size_t rowg = (size_t)b * SEQ + lt * 64;
    const size_t bh = (size_t)b * NH + h;

    uint32_t* Qh32 = (uint32_t*)g_Qh; uint32_t* Ql32 = (uint32_t*)g_Ql;
    uint32_t* Kh32 = (uint32_t*)g_Kh; uint32_t* Kl32 = (uint32_t*)g_Kl;
    uint32_t* Vh32 = (uint32_t*)g_Vh; uint32_t* Vl32 = (uint32_t*)g_Vl;

    const float nl = -0.194206455f;   // ln(500)/32
    #pragma unroll
    for (int i = 0; i < 4; i++) {
        int idx = i * 256 + tid;
        int r = idx >> 4, j = idx & 15;
        int l = lt * 64 + r;
        const float* row = qkv + (rowg + r) * L3;
        float f0 = expf((float)(2*j)     * nl);
        float f1 = expf((float)(2*j + 1) * nl);
        float s0, c0, s1, c1;
        sincosf((float)l * f0, &s0, &c0);
        sincosf((float)l * f1, &s1, &c1);
        size_t ob = (bh * SEQ + l) * 32;
        {
            const float* q = row + h * 64;
            float t1a = q[2*j], t1b = q[2*j+1], t2a = q[2*j+32], t2b = q[2*j+33];
            uint32_t hh, ll;
            split_pack2((t1a*c0 - t2a*s0) * 0.125f, (t1b*c1 - t2b*s1) * 0.125f, hh, ll);
            Qh32[ob + j] = hh;      Ql32[ob + j] = ll;
            split_pack2((t1a*s0 + t2a*c0) * 0.125f, (t1b*s1 + t2b*c1) * 0.125f, hh, ll);
            Qh32[ob + 16 + j] = hh; Ql32[ob + 16 + j] = ll;
        }
        {
            const float* k = row + 1024 + h * 64;
            float t1a = k[2*j], t1b = k[2*j+1], t2a = k[2*j+32], t2b = k[2*j+33];
            uint32_t hh, ll;
            split_pack2(t1a*c0 - t2a*s0, t1b*c1 - t2b*s1, hh, ll);
            Kh32[ob + j] = hh;      Kl32[ob + j] = ll;
            split_pack2(t1a*s0 + t2a*c0, t1b*s1 + t2b*c1, hh, ll);
            Kh32[ob + 16 + j] = hh; Kl32[ob + 16 + j] = ll;
        }
    }
    #pragma unroll
    for (int i = 0; i < 4; i++) {
        int idx = i * 256 + tid;
        int r = idx >> 4, c4 = (idx & 15) * 4;
        float4 v = *(const float4*)(qkv + (rowg + r) * L3 + 2048 + h * 64 + c4);
        vs[r][c4] = v.x; vs[r][c4+1] = v.y; vs[r][c4+2] = v.z; vs[r][c4+3] = v.w;
    }
    __syncthreads();
    #pragma unroll
    for (int i = 0; i < 8; i++) {
        int idx = i * 256 + tid;
        int d = idx >> 5, lp = idx & 31;
        uint32_t hh, ll;
        split_pack2(vs[2*lp][d], vs[2*lp+1][d], hh, ll);
        size_t o = (bh * 64 + d) * (SEQ/2) + lt * 32 + lp;
        Vh32[o] = hh; Vl32[o] = ll;
    }
}

// ---------------------------------------------------------------------------
// Split-bf16 GEMM + bias, mma.sync.  C[M,N] = A @ B^T + bias.
// CTA 256x128, 512 threads = 16 warps (4m x 4n), warp tile 64x32, BK=32.
// 3-stage cp.async ring with DISTANCE-2 prefetch; ONE __syncthreads per k-iter.
// Stage layout (61440 B): Ah[256x80] Al[256x80] Bh[128x80] Bl[128x80].
// ---------------------------------------------------------------------------
#define GS2_STAGE 61440
#define GS2_SMEM  (3*GS2_STAGE)

__global__ __launch_bounds__(512, 1)
void gemm_bf16(const __nv_bfloat16* __restrict__ Ahg, const __nv_bfloat16* __restrict__ Alg,
               const __nv_bfloat16* __restrict__ Bhg, const __nv_bfloat16* __restrict__ Blg,
               const float* __restrict__ bias, float* __restrict__ C,
               int M, int N, int K)
{
    extern __shared__ char smc[];
    const uint32_t smb = (uint32_t)__cvta_generic_to_shared(smc);
    const int tid = threadIdx.x, lane = tid & 31, wid = tid >> 5;
    const int wm = wid & 3, wn = wid >> 2;
    const int m0 = blockIdx.y * 256, n0 = blockIdx.x * 128;
    const int nk = K >> 5;

    // staging: A — one 64B row per thread (4 chunks); B — half row (2 chunks)
    const int arow = tid & 255;
    const char* aSrc = (const char*)((tid < 256 ? Ahg : Alg) + (size_t)(m0 + arow) * K);
    const uint32_t aDst = smb + (tid < 256 ? 0 : 20480) + arow * 80;
    const int brow = (tid & 255) >> 1;
    const int bhalf = tid & 1;
    const char* bSrc = (const char*)((tid < 256 ? Bhg : Blg) + (size_t)(n0 + brow) * K) + bhalf * 32;
    const uint32_t bDst = smb + 40960 + (tid < 256 ? 0 : 10240) + brow * 80 + bhalf * 32;

    #define G2_LOAD(s, kt) do { \
        const char* a_ = aSrc + (size_t)(kt) * 64; \
        const char* b_ = bSrc + (size_t)(kt) * 64; \
        uint32_t ad_ = aDst + (s) * GS2_STAGE, bd_ = bDst + (s) * GS2_STAGE; \
        CP16(ad_,      a_);       CP16(ad_ + 16, a_ + 16); \
        CP16(ad_ + 32, a_ + 32);  CP16(ad_ + 48, a_ + 48); \
        CP16(bd_,      b_);       CP16(bd_ + 16, b_ + 16); \
    } while (0)

    float acc[4][4][4];
    #pragma unroll
    for (int i = 0; i < 4; i++)
        #pragma unroll
        for (int j = 0; j < 4; j++)
            #pragma unroll
            for (int k = 0; k < 4; k++) acc[i][j][k] = 0.0f;

    const int rowA = ((lane >> 3) & 1) * 8 + (lane & 7);
    const int colA = (lane >> 4) * 16;
    const int rowB = (lane >> 4) * 8 + (lane & 7);
    const int colB = ((lane >> 3) & 1) * 16;

    G2_LOAD(0, 0); CPCOMMIT();
    G2_LOAD(1, 1); CPCOMMIT();

    for (int kt = 0; kt < nk; kt++) {
        CPWAIT1();            // stage kt resident (own thread)
        __syncthreads();      // all threads' stage-kt writes visible; iter kt-1 reads done
        if (kt + 2 < nk) G2_LOAD((kt + 2) % 3, kt + 2);
        CPCOMMIT();
        const uint32_t st = smb + (uint32_t)(kt % 3) * GS2_STAGE;

        #pragma unroll
        for (int ks = 0; ks < 2; ks++) {
            uint32_t ah[4][4], al_[4][4];
            #pragma unroll
            for (int mt = 0; mt < 4; mt++) {
                uint32_t aa = st + (uint32_t)(wm * 64 + mt * 16 + rowA) * 80 + ks * 32 + colA;
                LDSM4(ah[mt][0], ah[mt][1], ah[mt][2], ah[mt][3], aa);
                LDSM4(al_[mt][0], al_[mt][1], al_[mt][2], al_[mt][3], aa + 20480);
            }
            #pragma unroll
            for (int ntp = 0; ntp < 2; ntp++) {
                uint32_t ba = st + 40960 + (uint32_t)(wn * 32 + ntp * 16 + rowB) * 80 + ks * 32 + colB;
                uint32_t bh0, bh1, bh2, bh3, bl0, bl1, bl2, bl3;
                LDSM4(bh0, bh1, bh2, bh3, ba);
                LDSM4(bl0, bl1, bl2, bl3, ba + 10240);
                #pragma unroll
                for (int mt = 0; mt < 4; mt++) {
                    mma_bf16(acc[mt][2*ntp],   ah[mt][0], ah[mt][1], ah[mt][2], ah[mt][3], bh0, bh1);
                    mma_bf16(acc[mt][2*ntp],   ah[mt][0], ah[mt][1], ah[mt][2], ah[mt][3], bl0, bl1);
                    mma_bf16(acc[mt][2*ntp],   al_[mt][0], al_[mt][1], al_[mt][2], al_[mt][3], bh0, bh1);
                    mma_bf16(acc[mt][2*ntp+1], ah[mt][0], ah[mt][1], ah[mt][2], ah[mt][3], bh2, bh3);
                    mma_bf16(acc[mt][2*ntp+1], ah[mt][0], ah[mt][1], ah[mt][2], ah[mt][3], bl2, bl3);
                    mma_bf16(acc[mt][2*ntp+1], al_[mt][0], al_[mt][1], al_[mt][2], al_[mt][3], bh2, bh3);
                }
            }
        }
    }

    #pragma unroll
    for (int nt = 0; nt < 4; nt++) {
        int col = n0 + wn * 32 + nt * 8 + (lane & 3) * 2;
        float2 bs = *(const float2*)&bias[col];
        #pragma unroll
        for (int mt = 0; mt < 4; mt++) {
            int r = m0 + wm * 64 + mt * 16 + (lane >> 2);
            float2 v0 = { acc[mt][nt][0] + bs.x, acc[mt][nt][1] + bs.y };
            float2 v1 = { acc[mt][nt][2] + bs.x, acc[mt][nt][3] + bs.y };
            *(float2*)&C[(size_t)r * N + col]       = v0;
            *(float2*)&C[(size_t)(r + 8) * N + col] = v1;
        }
    }
}

// ---------------------------------------------------------------------------
// Flash attention (round-3 core; loop restructured to ONE sync per iter:
// wait -> sync -> issue prefetch -> compute).
// ---------------------------------------------------------------------------
#define FQ     36864
#define FSTAGE 36864
#define FSM    (FQ + 2*FSTAGE)

__global__ __launch_bounds__(256, 2)
void flash_bf16(const __nv_bfloat16* __restrict__ Qh, const __nv_bfloat16* __restrict__ Ql,
                const __nv_bfloat16* __restrict__ Kh, const __nv_bfloat16* __restrict__ Kl,
                const __nv_bfloat16* __restrict__ Vh, const __nv_bfloat16* __restrict__ Vl)
{
    extern __shared__ char smc[];
    const uint32_t smb = (uint32_t)__cvta_generic_to_shared(smc);
    const int tid = threadIdx.x, lane = tid & 31, wid = tid >> 5;
    const int qt = blockIdx.x, h = blockIdx.y, b = blockIdx.z;
    const size_t bh = (size_t)b * NH + h;

    {
        const int qtile = tid >> 7;
        const int qr = tid & 127;
        const __nv_bfloat16* qsrc = qtile ? Ql : Qh;
        const char* gq = (const char*)(qsrc + (bh * SEQ + (size_t)qt * 128 + qr) * 64);
        uint32_t sq = smb + qtile * 18432 + qr * 144;
        #pragma unroll
        for (int c = 0; c < 8; c++) CP16(sq + c*16, gq + c*16);
    }
    const int tile = tid >> 6;
    const int krow = tid & 63;
    const char* gkv;
    int gstride;
    if (tile == 0)      { gkv = (const char*)(Kh + (bh * SEQ + krow) * 64); gstride = 8192; }
    else if (tile == 1) { gkv = (const char*)(Kl + (bh * SEQ + krow) * 64); gstride = 8192; }
    else if (tile == 2) { gkv = (const char*)(Vh + (bh * 64 + krow) * SEQ); gstride = 128; }
    else                { gkv = (const char*)(Vl + (bh * 64 + krow) * SEQ); gstride = 128; }
    const uint32_t skv = smb + FQ + tile * 9216 + krow * 144;
    #pragma unroll
    for (int c = 0; c < 8; c++) CP16(skv + c*16, gkv + c*16);
    CPCOMMIT();

    float s[8][4], o[8][4];
    float m0r = -INFINITY, m1r = -INFINITY, l0r = 0.0f, l1r = 0.0f;
    #pragma unroll
    for (int i = 0; i < 8; i++)
        #pragma unroll
        for (int j = 0; j < 4; j++) o[i][j] = 0.0f;

    const int rowA = ((lane >> 3) & 1) * 8 + (lane & 7);
    const int colA = (lane >> 4) * 16;
    const int rowB = (lane >> 4) * 8 + (lane & 7);
    const int colB = ((lane >> 3) & 1) * 16;

    for (int t = 0; t < SEQ / 64; t++) {
        CPWAIT0();           // stage t resident (own thread)
        __syncthreads();     // visible to all; stage (t+1)&1 reads (iter t-1) done
        if (t < SEQ / 64 - 1) {
            const char* gp = gkv + (size_t)(t + 1) * gstride;
            uint32_t sp = skv + ((t + 1) & 1) * FSTAGE;
            #pragma unroll
            for (int c = 0; c < 8; c++) CP16(sp + c*16, gp + c*16);
        }
        CPCOMMIT();
        const uint32_t kvb = smb + FQ + (t & 1) * FSTAGE;

        #pragma unroll
        for (int i = 0; i < 8; i++)
            #pragma unroll
            for (int j = 0; j < 4; j++) s[i][j] = 0.0f;

        #pragma unroll
        for (int ks = 0; ks < 4; ks++) {
            uint32_t qa = smb + (uint32_t)(wid * 16 + rowA) * 144 + ks * 32 + colA;
            uint32_t qh0, qh1, qh2, qh3, ql0, ql1, ql2, ql3;
            LDSM4(qh0, qh1, qh2, qh3, qa);
            LDSM4(ql0, ql1, ql2, ql3, qa + 18432);
            #pragma unroll
            for (int ntp = 0; ntp < 4; ntp++) {
                uint32_t ka = kvb + (uint32_t)(ntp * 16 + rowB) * 144 + ks * 32 + colB;
                uint32_t kh0, kh1, kh2, kh3, kl0, kl1, kl2, kl3;
                LDSM4(kh0, kh1, kh2, kh3, ka);
                LDSM4(kl0, kl1, kl2, kl3, ka + 9216);
                mma_bf16(s[2*ntp],   qh0, qh1, qh2, qh3, kh0, kh1);
                mma_bf16(s[2*ntp],   qh0, qh1, qh2, qh3, kl0, kl1);
                mma_bf16(s[2*ntp],   ql0, ql1, ql2, ql3, kh0, kh1);
                mma_bf16(s[2*ntp+1], qh0, qh1, qh2, qh3, kh2, kh3);
                mma_bf16(s[2*ntp+1], qh0, qh1, qh2, qh3, kl2, kl3);
                mma_bf16(s[2*ntp+1], ql0, ql1, ql2, ql3, kh2, kh3);
            }
        }

        float mx0 = -INFINITY, mx1 = -INFINITY;
        #pragma unroll
        for (int nt = 0; nt < 8; nt++) {
            mx0 = fmaxf(mx0, fmaxf(s[nt][0], s[nt][1]));
            mx1 = fmaxf(mx1, fmaxf(s[nt][2], s[nt][3]));
        }
        mx0 = fmaxf(mx0, __shfl_xor_sync(0xffffffffu, mx0, 1));
        mx0 = fmaxf(mx0, __shfl_xor_sync(0xffffffffu, mx0, 2));
        mx1 = fmaxf(mx1, __shfl_xor_sync(0xffffffffu, mx1, 1));
        mx1 = fmaxf(mx1, __shfl_xor_sync(0xffffffffu, mx1, 2));
        float mn0 = fmaxf(m0r, mx0), mn1 = fmaxf(m1r, mx1);
        float a0 = __expf(m0r - mn0), a1 = __expf(m1r - mn1);
        float sum0 = 0.0f, sum1 = 0.0f;
        #pragma unroll
        for (int nt = 0; nt < 8; nt++) {
            s[nt][0] = __expf(s[nt][0] - mn0); sum0 += s[nt][0];
            s[nt][1] = __expf(s[nt][1] - mn0); sum0 += s[nt][1];
            s[nt][2] = __expf(s[nt][2] - mn1); sum1 += s[nt][2];
            s[nt][3] = __expf(s[nt][3] - mn1); sum1 += s[nt][3];
        }
        sum0 += __shfl_xor_sync(0xffffffffu, sum0, 1);
        sum0 += __shfl_xor_sync(0xffffffffu, sum0, 2);
        sum1 += __shfl_xor_sync(0xffffffffu, sum1, 1);
        sum1 += __shfl_xor_sync(0xffffffffu, sum1, 2);
        l0r = l0r * a0 + sum0;  l1r = l1r * a1 + sum1;
        m0r = mn0;              m1r = mn1;
        #pragma unroll
        for (int dt = 0; dt < 8; dt++) {
            o[dt][0] *= a0; o[dt][1] *= a0;
            o[dt][2] *= a1; o[dt][3] *= a1;
        }

        #pragma unroll
        for (int kt = 0; kt < 4; kt++) {
            uint32_t ah0, ah1, ah2, ah3, au0, au1, au2, au3;
            split_pack2(s[2*kt][0],   s[2*kt][1],   ah0, au0);
            split_pack2(s[2*kt][2],   s[2*kt][3],   ah1, au1);
            split_pack2(s[2*kt+1][0], s[2*kt+1][1], ah2, au2);
            split_pack2(s[2*kt+1][2], s[2*kt+1][3], ah3, au3);
            #pragma unroll
            for (int dtp = 0; dtp < 4; dtp++) {
                uint32_t va = kvb + 18432 + (uint32_t)(dtp * 16 + rowB) * 144 + kt * 32 + colB;
                uint32_t vh0, vh1, vh2, vh3, vl0, vl1, vl2, vl3;
                LDSM4(vh0, vh1, vh2, vh3, va);
                LDSM4(vl0, vl1, vl2, vl3, va + 9216);
                mma_bf16(o[2*dtp],   ah0, ah1, ah2, ah3, vh0, vh1);
                mma_bf16(o[2*dtp],   ah0, ah1, ah2, ah3, vl0, vl1);
                mma_bf16(o[2*dtp],   au0, au1, au2, au3, vh0, vh1);
                mma_bf16(o[2*dtp+1], ah0, ah1, ah2, ah3, vh2, vh3);
                mma_bf16(o[2*dtp+1], ah0, ah1, ah2, ah3, vl2, vl3);
                mma_bf16(o[2*dtp+1], au0, au1, au2, au3, vh2, vh3);
            }
        }
    }

    float inv0 = 1.0f / l0r, inv1 = 1.0f / l1r;
    const size_t row = (size_t)b * SEQ + (size_t)qt * 128 + wid * 16 + (lane >> 2);
    uint32_t* oh32 = (uint32_t*)g_ath;
    uint32_t* ol32 = (uint32_t*)g_atl;
    #pragma unroll
    for (int dt = 0; dt < 8; dt++) {
        int cp = h * 32 + dt * 4 + (lane & 3);
        uint32_t hh, ll;
        split_pack2(o[dt][0] * inv0, o[dt][1] * inv0, hh, ll);
        oh32[row * 512 + cp] = hh;       ol32[row * 512 + cp] = ll;
        split_pack2(o[dt][2] * inv1, o[dt][3] * inv1, hh, ll);
        oh32[(row + 8) * 512 + cp] = hh; ol32[(row + 8) * 512 + cp] = ll;
    }
}

// ---------------------------------------------------------------------------
// Launcher
// ---------------------------------------------------------------------------
extern "C" void kernel_launch(void* const* d_in, const int* in_sizes, int n_in,
                              void* d_out, int out_size)
{
    const float* x     = (const float*)d_in[0];
    const float* w_qkv = (const float*)d_in[1];
    const float* b_qkv = (const float*)d_in[2];
    const float* w_out = (const float*)d_in[3];
    const float* b_out = (const float*)d_in[4];
    float* out = (float*)d_out;

    float* qkvp;
    __nv_bfloat16 *xh, *xl, *wqh, *wql, *woh, *wol, *Qh, *Ql, *Kh, *Kl, *Vh, *Vl, *ath, *atl;
    cudaGetSymbolAddress((void**)&qkvp, g_qkv);
    cudaGetSymbolAddress((void**)&xh, g_xh);   cudaGetSymbolAddress((void**)&xl, g_xl);
    cudaGetSymbolAddress((void**)&wqh, g_wqh); cudaGetSymbolAddress((void**)&wql, g_wql);
    cudaGetSymbolAddress((void**)&woh, g_woh); cudaGetSymbolAddress((void**)&wol, g_wol);
    cudaGetSymbolAddress((void**)&Qh, g_Qh);   cudaGetSymbolAddress((void**)&Ql, g_Ql);
    cudaGetSymbolAddress((void**)&Kh, g_Kh);   cudaGetSymbolAddress((void**)&Kl, g_Kl);
    cudaGetSymbolAddress((void**)&Vh, g_Vh);   cudaGetSymbolAddress((void**)&Vl, g_Vl);
    cudaGetSymbolAddress((void**)&ath, g_ath); cudaGetSymbolAddress((void**)&atl, g_atl);

    cudaFuncSetAttribute(gemm_bf16,  cudaFuncAttributeMaxDynamicSharedMemorySize, GS2_SMEM);
    cudaFuncSetAttribute(flash_bf16, cudaFuncAttributeMaxDynamicSharedMemorySize, FSM);

    prep_wT<<<dim3(L3 / 32, DM / 32), 256>>>(w_qkv, wqh, wql, DM, L3);
    prep_wT<<<dim3(DM / 32, DM / 32), 256>>>(w_out, woh, wol, DM, DM);
    prep_x<<<(int)(((size_t)ROWS * DM / 2) / 256), 256>>>(x, xh, xl);

    // QKV projection: M=8192 (256-tiles), N=3072 (128-tiles)
    gemm_bf16<<<dim3(L3 / 128, ROWS / 256), 512, GS2_SMEM>>>(xh, xl, wqh, wql, b_qkv, qkvp,
                                                             ROWS, L3, DM);
    prep_qkv<<<dim3(SEQ / 64, NH, BATCH), 256>>>(qkvp);

    flash_bf16<<<dim3(SEQ / 128, NH, BATCH), 256, FSM>>>(Qh, Ql, Kh, Kl, Vh, Vl);

    // output projection
    gemm_bf16<<<dim3(DM / 128, ROWS / 256), 512, GS2_SMEM>>>(ath, atl, woh, wol, b_out, out,
                                                             ROWS, DM, DM);
}

// round 9
// speedup vs baseline: 1.0370x; 1.0012x over previous
#include <cuda_runtime.h>
#include <cuda_bf16.h>
#include <math.h>
#include <stdint.h>

#define BATCH 2
#define SEQ   4096
#define DM    1024
#define NH    16
#define DH    64
#define L3    3072
#define ROWS  (BATCH*SEQ)

// ---------------- device scratch (allocation-free) ----------------
__device__ float g_qkv[(size_t)ROWS * L3];
__device__ __nv_bfloat16 g_xh[(size_t)ROWS*DM],  g_xl[(size_t)ROWS*DM];
__device__ __nv_bfloat16 g_wqh[(size_t)DM*L3],   g_wql[(size_t)DM*L3];
__device__ __nv_bfloat16 g_woh[(size_t)DM*DM],   g_wol[(size_t)DM*DM];
__device__ __nv_bfloat16 g_Qh[(size_t)ROWS*DM],  g_Ql[(size_t)ROWS*DM];
__device__ __nv_bfloat16 g_Kh[(size_t)ROWS*DM],  g_Kl[(size_t)ROWS*DM];
__device__ __nv_bfloat16 g_Vh[(size_t)ROWS*DM],  g_Vl[(size_t)ROWS*DM];
__device__ __nv_bfloat16 g_ath[(size_t)ROWS*DM], g_atl[(size_t)ROWS*DM];

// ---------------- helpers ----------------
__device__ __forceinline__ uint32_t pack2(__nv_bfloat16 a, __nv_bfloat16 b) {
    __nv_bfloat162 t; t.x = a; t.y = b;
    return *reinterpret_cast<uint32_t*>(&t);
}
__device__ __forceinline__ void split1(float f, __nv_bfloat16& h, __nv_bfloat16& l) {
    h = __float2bfloat16_rn(f);
    l = __float2bfloat16_rn(f - __bfloat162float(h));
}
__device__ __forceinline__ void split_pack2(float f0, float f1, uint32_t& h, uint32_t& l) {
    __nv_bfloat16 h0, l0, h1, l1;
    split1(f0, h0, l0); split1(f1, h1, l1);
    h = pack2(h0, h1); l = pack2(l0, l1);
}
__device__ __forceinline__ void mma_bf16(float c[4],
                                         uint32_t a0, uint32_t a1, uint32_t a2, uint32_t a3,
                                         uint32_t b0, uint32_t b1) {
    asm volatile(
        "mma.sync.aligned.m16n8k16.row.col.f32.bf16.bf16.f32 "
        "{%0,%1,%2,%3}, {%4,%5,%6,%7}, {%8,%9}, {%0,%1,%2,%3};\n"
        : "+f"(c[0]), "+f"(c[1]), "+f"(c[2]), "+f"(c[3])
        : "r"(a0), "r"(a1), "r"(a2), "r"(a3), "r"(b0), "r"(b1));
}
#define LDSM4(r0,r1,r2,r3,addr) \
    asm volatile("ldmatrix.sync.aligned.m8n8.x4.shared.b16 {%0,%1,%2,%3}, [%4];" \
                 : "=r"(r0),"=r"(r1),"=r"(r2),"=r"(r3) : "r"(addr))
#define CP16(s,g)  asm volatile("cp.async.cg.shared.global [%0], [%1], 16;" :: "r"(s), "l"(g))
#define CPCOMMIT() asm volatile("cp.async.commit_group;" ::: "memory")
#define CPWAIT1()  asm volatile("cp.async.wait_group 1;" ::: "memory")
#define CPWAIT0()  asm volatile("cp.async.wait_group 0;" ::: "memory")

// ---------------- prep kernels ----------------
__global__ void prep_wT(const float* __restrict__ W,
                        __nv_bfloat16* __restrict__ WTh, __nv_bfloat16* __restrict__ WTl,
                        int K, int N)
{
    __shared__ float t[32][33];
    const int tid = threadIdx.x;
    const int n0 = blockIdx.x * 32, k0 = blockIdx.y * 32;
    #pragma unroll
    for (int i = 0; i < 4; i++) {
        int idx = i * 256 + tid;
        t[idx >> 5][idx & 31] = W[(size_t)(k0 + (idx >> 5)) * N + n0 + (idx & 31)];
    }
    __syncthreads();
    uint32_t* oh = (uint32_t*)WTh;
    uint32_t* ol = (uint32_t*)WTl;
    #pragma unroll
    for (int i = 0; i < 2; i++) {
        int idx = i * 256 + tid;
        int n = idx >> 4, kp = idx & 15;
        uint32_t h, l;
        split_pack2(t[2*kp][n], t[2*kp+1][n], h, l);
        size_t o = ((size_t)(n0 + n) * K + k0) / 2 + kp;
        oh[o] = h; ol[o] = l;
    }
}

__global__ void prep_x(const float* __restrict__ x,
                       __nv_bfloat16* __restrict__ xh, __nv_bfloat16* __restrict__ xl)
{
    size_t i = (size_t)blockIdx.x * 256 + threadIdx.x;
    float2 v = ((const float2*)x)[i];
    uint32_t h, l;
    split_pack2(v.x, v.y, h, l);
    ((uint32_t*)xh)[i] = h;
    ((uint32_t*)xl)[i] = l;
}

__global__ void prep_qkv(const float* __restrict__ qkv)
{
    __shared__ float vs[64][65];
    const int tid = threadIdx.x;
    const int lt = blockIdx.x, h = blockIdx.y, b = blockIdx.z;
    const size_t rowg = (size_t)b * SEQ + lt * 64;
    const size_t bh = (size_t)b * NH + h;

    uint32_t* Qh32 = (uint32_t*)g_Qh; uint32_t* Ql32 = (uint32_t*)g_Ql;
    uint32_t* Kh32 = (uint32_t*)g_Kh; uint32_t* Kl32 = (uint32_t*)g_Kl;
    uint32_t* Vh32 = (uint32_t*)g_Vh; uint32_t* Vl32 = (uint32_t*)g_Vl;

    const float nl = -0.194206455f;   // ln(500)/32
    #pragma unroll
    for (int i = 0; i < 4; i++) {
        int idx = i * 256 + tid;
        int r = idx >> 4, j = idx & 15;
        int l = lt * 64 + r;
        const float* row = qkv + (rowg + r) * L3;
        float f0 = expf((float)(2*j)     * nl);
        float f1 = expf((float)(2*j + 1) * nl);
        float s0, c0, s1, c1;
        sincosf((float)l * f0, &s0, &c0);
        sincosf((float)l * f1, &s1, &c1);
        size_t ob = (bh * SEQ + l) * 32;
        {
            const float* q = row + h * 64;
            float t1a = q[2*j], t1b = q[2*j+1], t2a = q[2*j+32], t2b = q[2*j+33];
            uint32_t hh, ll;
            split_pack2((t1a*c0 - t2a*s0) * 0.125f, (t1b*c1 - t2b*s1) * 0.125f, hh, ll);
            Qh32[ob + j] = hh;      Ql32[ob + j] = ll;
            split_pack2((t1a*s0 + t2a*c0) * 0.125f, (t1b*s1 + t2b*c1) * 0.125f, hh, ll);
            Qh32[ob + 16 + j] = hh; Ql32[ob + 16 + j] = ll;
        }
        {
            const float* k = row + 1024 + h * 64;
            float t1a = k[2*j], t1b = k[2*j+1], t2a = k[2*j+32], t2b = k[2*j+33];
            uint32_t hh, ll;
            split_pack2(t1a*c0 - t2a*s0, t1b*c1 - t2b*s1, hh, ll);
            Kh32[ob + j] = hh;      Kl32[ob + j] = ll;
            split_pack2(t1a*s0 + t2a*c0, t1b*s1 + t2b*c1, hh, ll);
            Kh32[ob + 16 + j] = hh; Kl32[ob + 16 + j] = ll;
        }
    }
    #pragma unroll
    for (int i = 0; i < 4; i++) {
        int idx = i * 256 + tid;
        int r = idx >> 4, c4 = (idx & 15) * 4;
        float4 v = *(const float4*)(qkv + (rowg + r) * L3 + 2048 + h * 64 + c4);
        vs[r][c4] = v.x; vs[r][c4+1] = v.y; vs[r][c4+2] = v.z; vs[r][c4+3] = v.w;
    }
    __syncthreads();
    #pragma unroll
    for (int i = 0; i < 8; i++) {
        int idx = i * 256 + tid;
        int d = idx >> 5, lp = idx & 31;
        uint32_t hh, ll;
        split_pack2(vs[2*lp][d], vs[2*lp+1][d], hh, ll);
        size_t o = (bh * 64 + d) * (SEQ/2) + lt * 32 + lp;
        Vh32[o] = hh; Vl32[o] = ll;
    }
}

// ---------------------------------------------------------------------------
// Split-bf16 GEMM + bias, mma.sync.  Round-8 structure, but MMAs reordered
// TERM-MAJOR: all hh across accumulators, then hl, then lh — RAW chain
// distance goes 1 -> 8 independent MMAs.
// ---------------------------------------------------------------------------
#define GS2_STAGE 61440
#define GS2_SMEM  (3*GS2_STAGE)

__global__ __launch_bounds__(512, 1)
void gemm_bf16(const __nv_bfloat16* __restrict__ Ahg, const __nv_bfloat16* __restrict__ Alg,
               const __nv_bfloat16* __restrict__ Bhg, const __nv_bfloat16* __restrict__ Blg,
               const float* __restrict__ bias, float* __restrict__ C,
               int M, int N, int K)
{
    extern __shared__ char smc[];
    const uint32_t smb = (uint32_t)__cvta_generic_to_shared(smc);
    const int tid = threadIdx.x, lane = tid & 31, wid = tid >> 5;
    const int wm = wid & 3, wn = wid >> 2;
    const int m0 = blockIdx.y * 256, n0 = blockIdx.x * 128;
    const int nk = K >> 5;

    const int arow = tid & 255;
    const char* aSrc = (const char*)((tid < 256 ? Ahg : Alg) + (size_t)(m0 + arow) * K);
    const uint32_t aDst = smb + (tid < 256 ? 0 : 20480) + arow * 80;
    const int brow = (tid & 255) >> 1;
    const int bhalf = tid & 1;
    const char* bSrc = (const char*)((tid < 256 ? Bhg : Blg) + (size_t)(n0 + brow) * K) + bhalf * 32;
    const uint32_t bDst = smb + 40960 + (tid < 256 ? 0 : 10240) + brow * 80 + bhalf * 32;

    #define G2_LOAD(s, kt) do { \
        const char* a_ = aSrc + (size_t)(kt) * 64; \
        const char* b_ = bSrc + (size_t)(kt) * 64; \
        uint32_t ad_ = aDst + (s) * GS2_STAGE, bd_ = bDst + (s) * GS2_STAGE; \
        CP16(ad_,      a_);       CP16(ad_ + 16, a_ + 16); \
        CP16(ad_ + 32, a_ + 32);  CP16(ad_ + 48, a_ + 48); \
        CP16(bd_,      b_);       CP16(bd_ + 16, b_ + 16); \
    } while (0)

    float acc[4][4][4];
    #pragma unroll
    for (int i = 0; i < 4; i++)
        #pragma unroll
        for (int j = 0; j < 4; j++)
            #pragma unroll
            for (int k = 0; k < 4; k++) acc[i][j][k] = 0.0f;

    const int rowA = ((lane >> 3) & 1) * 8 + (lane & 7);
    const int colA = (lane >> 4) * 16;
    const int rowB = (lane >> 4) * 8 + (lane & 7);
    const int colB = ((lane >> 3) & 1) * 16;

    G2_LOAD(0, 0); CPCOMMIT();
    G2_LOAD(1, 1); CPCOMMIT();

    for (int kt = 0; kt < nk; kt++) {
        CPWAIT1();
        __syncthreads();
        if (kt + 2 < nk) G2_LOAD((kt + 2) % 3, kt + 2);
        CPCOMMIT();
        const uint32_t st = smb + (uint32_t)(kt % 3) * GS2_STAGE;

        #pragma unroll
        for (int ks = 0; ks < 2; ks++) {
            uint32_t ah[4][4], al_[4][4];
            #pragma unroll
            for (int mt = 0; mt < 4; mt++) {
                uint32_t aa = st + (uint32_t)(wm * 64 + mt * 16 + rowA) * 80 + ks * 32 + colA;
                LDSM4(ah[mt][0], ah[mt][1], ah[mt][2], ah[mt][3], aa);
                LDSM4(al_[mt][0], al_[mt][1], al_[mt][2], al_[mt][3], aa + 20480);
            }
            #pragma unroll
            for (int ntp = 0; ntp < 2; ntp++) {
                uint32_t ba = st + 40960 + (uint32_t)(wn * 32 + ntp * 16 + rowB) * 80 + ks * 32 + colB;
                uint32_t bh0, bh1, bh2, bh3, bl0, bl1, bl2, bl3;
                LDSM4(bh0, bh1, bh2, bh3, ba);
                LDSM4(bl0, bl1, bl2, bl3, ba + 10240);
                // term sweep 1: Ah*Bh — 8 independent MMAs
                #pragma unroll
                for (int mt = 0; mt < 4; mt++) {
                    mma_bf16(acc[mt][2*ntp],   ah[mt][0], ah[mt][1], ah[mt][2], ah[mt][3], bh0, bh1);
                    mma_bf16(acc[mt][2*ntp+1], ah[mt][0], ah[mt][1], ah[mt][2], ah[mt][3], bh2, bh3);
                }
                // term sweep 2: Ah*Bl
                #pragma unroll
                for (int mt = 0; mt < 4; mt++) {
                    mma_bf16(acc[mt][2*ntp],   ah[mt][0], ah[mt][1], ah[mt][2], ah[mt][3], bl0, bl1);
                    mma_bf16(acc[mt][2*ntp+1], ah[mt][0], ah[mt][1], ah[mt][2], ah[mt][3], bl2, bl3);
                }
                // term sweep 3: Al*Bh
                #pragma unroll
                for (int mt = 0; mt < 4; mt++) {
                    mma_bf16(acc[mt][2*ntp],   al_[mt][0], al_[mt][1], al_[mt][2], al_[mt][3], bh0, bh1);
                    mma_bf16(acc[mt][2*ntp+1], al_[mt][0], al_[mt][1], al_[mt][2], al_[mt][3], bh2, bh3);
                }
            }
        }
    }

    #pragma unroll
    for (int nt = 0; nt < 4; nt++) {
        int col = n0 + wn * 32 + nt * 8 + (lane & 3) * 2;
        float2 bs = *(const float2*)&bias[col];
        #pragma unroll
        for (int mt = 0; mt < 4; mt++) {
            int r = m0 + wm * 64 + mt * 16 + (lane >> 2);
            float2 v0 = { acc[mt][nt][0] + bs.x, acc[mt][nt][1] + bs.y };
            float2 v1 = { acc[mt][nt][2] + bs.x, acc[mt][nt][3] + bs.y };
            *(float2*)&C[(size_t)r * N + col]       = v0;
            *(float2*)&C[(size_t)(r + 8) * N + col] = v1;
        }
    }
}

// ---------------------------------------------------------------------------
// Flash attention.  Round-8 structure; S-loop and PV-loop reordered term-major
// over PAIRS of n/d tiles (RAW chain distance 1 -> 4, regs stay under 128).
// ---------------------------------------------------------------------------
#define FQ     36864
#define FSTAGE 36864
#define FSM    (FQ + 2*FSTAGE)

__global__ __launch_bounds__(256, 2)
void flash_bf16(const __nv_bfloat16* __restrict__ Qh, const __nv_bfloat16* __restrict__ Ql,
                const __nv_bfloat16* __restrict__ Kh, const __nv_bfloat16* __restrict__ Kl,
                const __nv_bfloat16* __restrict__ Vh, const __nv_bfloat16* __restrict__ Vl)
{
    extern __shared__ char smc[];
    const uint32_t smb = (uint32_t)__cvta_generic_to_shared(smc);
    const int tid = threadIdx.x, lane = tid & 31, wid = tid >> 5;
    const int qt = blockIdx.x, h = blockIdx.y, b = blockIdx.z;
    const size_t bh = (size_t)b * NH + h;

    {
        const int qtile = tid >> 7;
        const int qr = tid & 127;
        const __nv_bfloat16* qsrc = qtile ? Ql : Qh;
        const char* gq = (const char*)(qsrc + (bh * SEQ + (size_t)qt * 128 + qr) * 64);
        uint32_t sq = smb + qtile * 18432 + qr * 144;
        #pragma unroll
        for (int c = 0; c < 8; c++) CP16(sq + c*16, gq + c*16);
    }
    const int tile = tid >> 6;
    const int krow = tid & 63;
    const char* gkv;
    int gstride;
    if (tile == 0)      { gkv = (const char*)(Kh + (bh * SEQ + krow) * 64); gstride = 8192; }
    else if (tile == 1) { gkv = (const char*)(Kl + (bh * SEQ + krow) * 64); gstride = 8192; }
    else if (tile == 2) { gkv = (const char*)(Vh + (bh * 64 + krow) * SEQ); gstride = 128; }
    else                { gkv = (const char*)(Vl + (bh * 64 + krow) * SEQ); gstride = 128; }
    const uint32_t skv = smb + FQ + tile * 9216 + krow * 144;
    #pragma unroll
    for (int c = 0; c < 8; c++) CP16(skv + c*16, gkv + c*16);
    CPCOMMIT();

    float s[8][4], o[8][4];
    float m0r = -INFINITY, m1r = -INFINITY, l0r = 0.0f, l1r = 0.0f;
    #pragma unroll
    for (int i = 0; i < 8; i++)
        #pragma unroll
        for (int j = 0; j < 4; j++) o[i][j] = 0.0f;

    const int rowA = ((lane >> 3) & 1) * 8 + (lane & 7);
    const int colA = (lane >> 4) * 16;
    const int rowB = (lane >> 4) * 8 + (lane & 7);
    const int colB = ((lane >> 3) & 1) * 16;

    for (int t = 0; t < SEQ / 64; t++) {
        CPWAIT0();
        __syncthreads();
        if (t < SEQ / 64 - 1) {
            const char* gp = gkv + (size_t)(t + 1) * gstride;
            uint32_t sp = skv + ((t + 1) & 1) * FSTAGE;
            #pragma unroll
            for (int c = 0; c < 8; c++) CP16(sp + c*16, gp + c*16);
        }
        CPCOMMIT();
        const uint32_t kvb = smb + FQ + (t & 1) * FSTAGE;

        #pragma unroll
        for (int i = 0; i < 8; i++)
            #pragma unroll
            for (int j = 0; j < 4; j++) s[i][j] = 0.0f;

        // ---- S = Q K^T, term-major over pairs of n-tiles
        #pragma unroll
        for (int ks = 0; ks < 4; ks++) {
            uint32_t qa = smb + (uint32_t)(wid * 16 + rowA) * 144 + ks * 32 + colA;
            uint32_t qh0, qh1, qh2, qh3, ql0, ql1, ql2, ql3;
            LDSM4(qh0, qh1, qh2, qh3, qa);
            LDSM4(ql0, ql1, ql2, ql3, qa + 18432);
            #pragma unroll
            for (int np = 0; np < 2; np++) {
                uint32_t kh[2][4], kl[2][4];
                #pragma unroll
                for (int p = 0; p < 2; p++) {
                    uint32_t ka = kvb + (uint32_t)((np*2+p) * 16 + rowB) * 144 + ks * 32 + colB;
                    LDSM4(kh[p][0], kh[p][1], kh[p][2], kh[p][3], ka);
                    LDSM4(kl[p][0], kl[p][1], kl[p][2], kl[p][3], ka + 9216);
                }
                // sweep hh (4 independent)
                #pragma unroll
                for (int p = 0; p < 2; p++) {
                    mma_bf16(s[2*(np*2+p)],   qh0, qh1, qh2, qh3, kh[p][0], kh[p][1]);
                    mma_bf16(s[2*(np*2+p)+1], qh0, qh1, qh2, qh3, kh[p][2], kh[p][3]);
                }
                // sweep hl
                #pragma unroll
                for (int p = 0; p < 2; p++) {
                    mma_bf16(s[2*(np*2+p)],   qh0, qh1, qh2, qh3, kl[p][0], kl[p][1]);
                    mma_bf16(s[2*(np*2+p)+1], qh0, qh1, qh2, qh3, kl[p][2], kl[p][3]);
                }
                // sweep lh
                #pragma unroll
                for (int p = 0; p < 2; p++) {
                    mma_bf16(s[2*(np*2+p)],   ql0, ql1, ql2, ql3, kh[p][0], kh[p][1]);
                    mma_bf16(s[2*(np*2+p)+1], ql0, ql1, ql2, ql3, kh[p][2], kh[p][3]);
                }
            }
        }

        // ---- online softmax
        float mx0 = -INFINITY, mx1 = -INFINITY;
        #pragma unroll
        for (int nt = 0; nt < 8; nt++) {
            mx0 = fmaxf(mx0, fmaxf(s[nt][0], s[nt][1]));
            mx1 = fmaxf(mx1, fmaxf(s[nt][2], s[nt][3]));
        }
        mx0 = fmaxf(mx0, __shfl_xor_sync(0xffffffffu, mx0, 1));
        mx0 = fmaxf(mx0, __shfl_xor_sync(0xffffffffu, mx0, 2));
        mx1 = fmaxf(mx1, __shfl_xor_sync(0xffffffffu, mx1, 1));
        mx1 = fmaxf(mx1, __shfl_xor_sync(0xffffffffu, mx1, 2));
        float mn0 = fmaxf(m0r, mx0), mn1 = fmaxf(m1r, mx1);
        float a0 = __expf(m0r - mn0), a1 = __expf(m1r - mn1);
        float sum0 = 0.0f, sum1 = 0.0f;
        #pragma unroll
        for (int nt = 0; nt < 8; nt++) {
            s[nt][0] = __expf(s[nt][0] - mn0); sum0 += s[nt][0];
            s[nt][1] = __expf(s[nt][1] - mn0); sum0 += s[nt][1];
            s[nt][2] = __expf(s[nt][2] - mn1); sum1 += s[nt][2];
            s[nt][3] = __expf(s[nt][3] - mn1); sum1 += s[nt][3];
        }
        sum0 += __shfl_xor_sync(0xffffffffu, sum0, 1);
        sum0 += __shfl_xor_sync(0xffffffffu, sum0, 2);
        sum1 += __shfl_xor_sync(0xffffffffu, sum1, 1);
        sum1 += __shfl_xor_sync(0xffffffffu, sum1, 2);
        l0r = l0r * a0 + sum0;  l1r = l1r * a1 + sum1;
        m0r = mn0;              m1r = mn1;
        #pragma unroll
        for (int dt = 0; dt < 8; dt++) {
            o[dt][0] *= a0; o[dt][1] *= a0;
            o[dt][2] *= a1; o[dt][3] *= a1;
        }

        // ---- O += P V, term-major over pairs of d-tiles
        #pragma unroll
        for (int kt = 0; kt < 4; kt++) {
            uint32_t ah0, ah1, ah2, ah3, au0, au1, au2, au3;
            split_pack2(s[2*kt][0],   s[2*kt][1],   ah0, au0);
            split_pack2(s[2*kt][2],   s[2*kt][3],   ah1, au1);
            split_pack2(s[2*kt+1][0], s[2*kt+1][1], ah2, au2);
            split_pack2(s[2*kt+1][2], s[2*kt+1][3], ah3, au3);
            #pragma unroll
            for (int dp = 0; dp < 2; dp++) {
                uint32_t vh[2][4], vl[2][4];
                #pragma unroll
                for (int p = 0; p < 2; p++) {
                    uint32_t va = kvb + 18432 + (uint32_t)((dp*2+p) * 16 + rowB) * 144 + kt * 32 + colB;
                    LDSM4(vh[p][0], vh[p][1], vh[p][2], vh[p][3], va);
                    LDSM4(vl[p][0], vl[p][1], vl[p][2], vl[p][3], va + 9216);
                }
                // sweep hh
                #pragma unroll
                for (int p = 0; p < 2; p++) {
                    mma_bf16(o[2*(dp*2+p)],   ah0, ah1, ah2, ah3, vh[p][0], vh[p][1]);
                    mma_bf16(o[2*(dp*2+p)+1], ah0, ah1, ah2, ah3, vh[p][2], vh[p][3]);
                }
                // sweep hl
                #pragma unroll
                for (int p = 0; p < 2; p++) {
                    mma_bf16(o[2*(dp*2+p)],   ah0, ah1, ah2, ah3, vl[p][0], vl[p][1]);
                    mma_bf16(o[2*(dp*2+p)+1], ah0, ah1, ah2, ah3, vl[p][2], vl[p][3]);
                }
                // sweep lh
                #pragma unroll
                for (int p = 0; p < 2; p++) {
                    mma_bf16(o[2*(dp*2+p)],   au0, au1, au2, au3, vh[p][0], vh[p][1]);
                    mma_bf16(o[2*(dp*2+p)+1], au0, au1, au2, au3, vh[p][2], vh[p][3]);
                }
            }
        }
    }

    float inv0 = 1.0f / l0r, inv1 = 1.0f / l1r;
    const size_t row = (size_t)b * SEQ + (size_t)qt * 128 + wid * 16 + (lane >> 2);
    uint32_t* oh32 = (uint32_t*)g_ath;
    uint32_t* ol32 = (uint32_t*)g_atl;
    #pragma unroll
    for (int dt = 0; dt < 8; dt++) {
        int cp = h * 32 + dt * 4 + (lane & 3);
        uint32_t hh, ll;
        split_pack2(o[dt][0] * inv0, o[dt][1] * inv0, hh, ll);
        oh32[row * 512 + cp] = hh;       ol32[row * 512 + cp] = ll;
        split_pack2(o[dt][2] * inv1, o[dt][3] * inv1, hh, ll);
        oh32[(row + 8) * 512 + cp] = hh; ol32[(row + 8) * 512 + cp] = ll;
    }
}

// ---------------------------------------------------------------------------
// Launcher
// ---------------------------------------------------------------------------
extern "C" void kernel_launch(void* const* d_in, const int* in_sizes, int n_in,
                              void* d_out, int out_size)
{
    const float* x     = (const float*)d_in[0];
    const float* w_qkv = (const float*)d_in[1];
    const float* b_qkv = (const float*)d_in[2];
    const float* w_out = (const float*)d_in[3];
    const float* b_out = (const float*)d_in[4];
    float* out = (float*)d_out;

    float* qkvp;
    __nv_bfloat16 *xh, *xl, *wqh, *wql, *woh, *wol, *Qh, *Ql, *Kh, *Kl, *Vh, *Vl, *ath, *atl;
    cudaGetSymbolAddress((void**)&qkvp, g_qkv);
    cudaGetSymbolAddress((void**)&xh, g_xh);   cudaGetSymbolAddress((void**)&xl, g_xl);
    cudaGetSymbolAddress((void**)&wqh, g_wqh); cudaGetSymbolAddress((void**)&wql, g_wql);
    cudaGetSymbolAddress((void**)&woh, g_woh); cudaGetSymbolAddress((void**)&wol, g_wol);
    cudaGetSymbolAddress((void**)&Qh, g_Qh);   cudaGetSymbolAddress((void**)&Ql, g_Ql);
    cudaGetSymbolAddress((void**)&Kh, g_Kh);   cudaGetSymbolAddress((void**)&Kl, g_Kl);
    cudaGetSymbolAddress((void**)&Vh, g_Vh);   cudaGetSymbolAddress((void**)&Vl, g_Vl);
    cudaGetSymbolAddress((void**)&ath, g_ath); cudaGetSymbolAddress((void**)&atl, g_atl);

    cudaFuncSetAttribute(gemm_bf16,  cudaFuncAttributeMaxDynamicSharedMemorySize, GS2_SMEM);
    cudaFuncSetAttribute(flash_bf16, cudaFuncAttributeMaxDynamicSharedMemorySize, FSM);

    prep_wT<<<dim3(L3 / 32, DM / 32), 256>>>(w_qkv, wqh, wql, DM, L3);
    prep_wT<<<dim3(DM / 32, DM / 32), 256>>>(w_out, woh, wol, DM, DM);
    prep_x<<<(int)(((size_t)ROWS * DM / 2) / 256), 256>>>(x, xh, xl);

    gemm_bf16<<<dim3(L3 / 128, ROWS / 256), 512, GS2_SMEM>>>(xh, xl, wqh, wql, b_qkv, qkvp,
                                                             ROWS, L3, DM);
    prep_qkv<<<dim3(SEQ / 64, NH, BATCH), 256>>>(qkvp);

    flash_bf16<<<dim3(SEQ / 128, NH, BATCH), 256, FSM>>>(Qh, Ql, Kh, Kl, Vh, Vl);

    gemm_bf16<<<dim3(DM / 128, ROWS / 256), 512, GS2_SMEM>>>(ath, atl, woh, wol, b_out, out,
                                                             ROWS, DM, DM);
}